// round 13
// baseline (speedup 1.0000x reference)
#include <cuda_runtime.h>
#include <cuda_fp16.h>
#include <cstdint>

#define Nn   50000
#define IND  1024
#define HID  128
#define OUTD 32
#define RR   4
#define EE   1600000

#define BK     32
#define NCHUNK (IND / BK)             // 32
#define MTILES ((Nn + 127) / 128)     // 391

#define TILE_B  10240                 // 128 rows * 80B (32 fp16 = 64B + 16B pad)
#define STAGE_B (2 * TILE_B)          // A, B
#define SMEM_SZ (2 * STAGE_B)         // 40960 bytes, double-buffered

#define GEMM2_SMEM ((RR + 1) * HID * OUTD * 4)   // 81920 bytes

#define SCAN_NB ((Nn + 1023) / 1024)  // 49

// ---------------- device scratch ----------------
__device__ float g_H1[(size_t)RR * Nn * HID];
__device__ float g_h   [(size_t)Nn * HID];     // root+b from gemm z=4
__device__ float g_hacc[(size_t)Nn * HID];     // edge aggregation accumulator
__device__ float g_H2[(size_t)RR * Nn * OUTD];
__device__ float g_norm[Nn * RR];
__device__ int   g_cnt [Nn * RR];
__device__ int   g_rowptr[Nn + 1];
__device__ int   g_woff  [Nn];
__device__ int   g_bsum  [SCAN_NB];
__device__ int   g_boff  [SCAN_NB];
__device__ uint32_t g_eidx[EE];
__device__ __align__(16) __half g_xh[(size_t)Nn * IND];
__device__ __align__(16) __half g_wt[(size_t)(RR + 1) * HID * IND];  // [z][n][k]

// ---------------- PTX helpers (baseline ISA only — no tcgen05) ----------------
__device__ __forceinline__ uint32_t smem_u32(const void* p) {
    uint32_t a;
    asm("{ .reg .u64 t; cvta.to.shared.u64 t, %1; cvt.u32.u64 %0, t; }" : "=r"(a) : "l"(p));
    return a;
}

__device__ __forceinline__ void cp16(uint32_t dst, const void* src, int ok) {
    asm volatile("cp.async.cg.shared.global [%0], [%1], 16, %2;"
                 :: "r"(dst), "l"(src), "r"(ok ? 16 : 0) : "memory");
}
#define CP_COMMIT() asm volatile("cp.async.commit_group;" ::: "memory")
#define CP_WAIT(n)  asm volatile("cp.async.wait_group %0;" :: "n"(n) : "memory")

__device__ __forceinline__ void ldm_x4(uint32_t* r, uint32_t addr) {
    asm volatile("ldmatrix.sync.aligned.m8n8.x4.shared.b16 {%0,%1,%2,%3}, [%4];"
                 : "=r"(r[0]), "=r"(r[1]), "=r"(r[2]), "=r"(r[3]) : "r"(addr));
}

__device__ __forceinline__ void mma_fp16(float* c, const uint32_t* a, const uint32_t* b) {
    asm volatile("mma.sync.aligned.m16n8k16.row.col.f32.f16.f16.f32 "
                 "{%0,%1,%2,%3}, {%4,%5,%6,%7}, {%8,%9}, {%0,%1,%2,%3};"
                 : "+f"(c[0]), "+f"(c[1]), "+f"(c[2]), "+f"(c[3])
                 : "r"(a[0]), "r"(a[1]), "r"(a[2]), "r"(a[3]), "r"(b[0]), "r"(b[1]));
}

// ---------------- conversion kernels ----------------
__global__ void conv_x_k(const float* __restrict__ x) {
    size_t total = (size_t)Nn * IND / 4;
    size_t stride = (size_t)gridDim.x * blockDim.x;
    const float4* x4 = (const float4*)x;
    uint2* xo = (uint2*)g_xh;
    for (size_t i = blockIdx.x * (size_t)blockDim.x + threadIdx.x; i < total; i += stride) {
        float4 v = x4[i];
        half2 p0 = __floats2half2_rn(v.x, v.y);
        half2 p1 = __floats2half2_rn(v.z, v.w);
        xo[i] = make_uint2(*(uint32_t*)&p0, *(uint32_t*)&p1);
    }
}

// tiled transpose: W [z][k][n] fp32 -> g_wt [z][n][k] fp16, both sides coalesced
__global__ __launch_bounds__(256) void conv_w_t(const float* __restrict__ W1,
                                                const float* __restrict__ root1)
{
    __shared__ float t[32][33];
    const int z = blockIdx.z;
    const int kt = blockIdx.x * 32;
    const int nt = blockIdx.y * 32;
    const int tx = threadIdx.x & 31, ty = threadIdx.x >> 5;   // 32 x 8
    const float* B = (z < RR) ? (W1 + (size_t)z * IND * HID) : root1;

    #pragma unroll
    for (int j = 0; j < 4; j++)
        t[ty + j * 8][tx] = B[(size_t)(kt + ty + j * 8) * HID + nt + tx];
    __syncthreads();

    #pragma unroll
    for (int j = 0; j < 4; j++) {
        float w = t[tx][ty + j * 8];
        size_t o = (size_t)z * HID * IND + (size_t)(nt + ty + j * 8) * IND + kt + tx;
        g_wt[o] = __float2half_rn(w);
    }
}

// ---------------- layer-1 GEMM: single-pass fp16 mma.sync, cp.async double-buffered ----------------
// zbase+blockIdx.z selects weight set; z<4 -> g_H1[z], z==4 -> root (+b1) -> g_h
__global__ __launch_bounds__(256) void gemm1_mma(const float* __restrict__ b1, int zbase) {
    extern __shared__ __align__(16) char smem[];
    const int tid = threadIdx.x, lane = tid & 31, wid = tid >> 5;
    const int wm = wid & 3, wn = wid >> 2;          // 4 m-warps x 2 n-warps
    const int rowBase = blockIdx.x * 128;
    const int z = zbase + blockIdx.z;
    const uint32_t sb = smem_u32(smem);

    const uint4* __restrict__ xh = (const uint4*)g_xh;
    const uint4* __restrict__ wh = (const uint4*)g_wt + (size_t)z * HID * (IND / 8);

    float acc[2][8][4];
    #pragma unroll
    for (int i = 0; i < 2; i++)
        #pragma unroll
        for (int j = 0; j < 8; j++)
            #pragma unroll
            for (int k = 0; k < 4; k++) acc[i][j][k] = 0.f;

    auto issue = [&](int stage, int ch) {
        uint32_t s = sb + stage * STAGE_B;
        #pragma unroll
        for (int i = 0; i < 2; i++) {
            int idx = i * 256 + tid;          // 0..511
            int r = idx >> 2, c = idx & 3;
            int row = rowBase + r;
            const uint4* src = xh + (size_t)row * (IND / 8) + ch * 4 + c;
            cp16(s + r * 80 + c * 16, src, row < Nn);
        }
        #pragma unroll
        for (int i = 0; i < 2; i++) {
            int idx = i * 256 + tid;
            int r = idx >> 2, c = idx & 3;
            const uint4* src = wh + (size_t)r * (IND / 8) + ch * 4 + c;
            cp16(s + TILE_B + r * 80 + c * 16, src, 1);
        }
    };

    issue(0, 0);
    CP_COMMIT();

    for (int ch = 0; ch < NCHUNK; ch++) {
        int st = ch & 1;
        if (ch + 1 < NCHUNK) {
            issue(st ^ 1, ch + 1);
            CP_COMMIT();
            CP_WAIT(1);
        } else {
            CP_WAIT(0);
        }
        __syncthreads();

        uint32_t sA = sb + st * STAGE_B;
        uint32_t sB = sA + TILE_B;

        #pragma unroll
        for (int ks = 0; ks < 2; ks++) {
            uint32_t ah[2][4], b[8][2];
            #pragma unroll
            for (int mi = 0; mi < 2; mi++) {
                int arow = wm * 32 + mi * 16 + (lane & 15);
                uint32_t off = arow * 80 + ks * 32 + ((lane >> 4) << 4);
                ldm_x4(ah[mi], sA + off);
            }
            #pragma unroll
            for (int j = 0; j < 4; j++) {
                int brow = wn * 64 + j * 16 + ((lane >> 4) << 3) + (lane & 7);
                uint32_t off = brow * 80 + ks * 32 + (((lane >> 3) & 1) << 4);
                uint32_t r[4];
                ldm_x4(r, sB + off);
                b[2 * j][0] = r[0]; b[2 * j][1] = r[1];
                b[2 * j + 1][0] = r[2]; b[2 * j + 1][1] = r[3];
            }
            #pragma unroll
            for (int mi = 0; mi < 2; mi++)
                #pragma unroll
                for (int ni = 0; ni < 8; ni++)
                    mma_fp16(acc[mi][ni], ah[mi], b[ni]);
        }
        __syncthreads();
    }

    float* C = (z < RR) ? (g_H1 + (size_t)z * Nn * HID) : g_h;
    #pragma unroll
    for (int mi = 0; mi < 2; mi++) {
        #pragma unroll
        for (int half = 0; half < 2; half++) {
            int row = rowBase + wm * 32 + mi * 16 + (lane >> 2) + half * 8;
            if (row >= Nn) continue;
            #pragma unroll
            for (int ni = 0; ni < 8; ni++) {
                int col = wn * 64 + ni * 8 + (lane & 3) * 2;
                float v0 = acc[mi][ni][half * 2 + 0];
                float v1 = acc[mi][ni][half * 2 + 1];
                if (z == RR) { v0 += __ldg(b1 + col); v1 += __ldg(b1 + col + 1); }
                *(float2*)(C + (size_t)row * HID + col) = make_float2(v0, v1);
            }
        }
    }
}

// ---------------- degree count / norm ----------------
__global__ void zero_cnt_k() {
    int i = blockIdx.x * blockDim.x + threadIdx.x;
    if (i < Nn * RR) g_cnt[i] = 0;
}

__global__ void count_k(const int* __restrict__ dst, const int* __restrict__ et) {
    int stride = gridDim.x * blockDim.x;
    for (int e = blockIdx.x * blockDim.x + threadIdx.x; e < EE; e += stride)
        atomicAdd(&g_cnt[dst[e] * RR + et[e]], 1);
}

__global__ void norm_k() {
    int i = blockIdx.x * blockDim.x + threadIdx.x;
    if (i < Nn * RR) {
        int c = g_cnt[i];
        g_norm[i] = 1.0f / (float)(c > 0 ? c : 1);
    }
}

// ---------------- CSR build: hierarchical scan (3 kernels), then edge fill ----------------
__global__ __launch_bounds__(1024) void scanA_k() {
    __shared__ int sh_w[32];
    const int tid = threadIdx.x, lane = tid & 31, warp = tid >> 5;
    int i = blockIdx.x * 1024 + tid;
    int d = 0;
    if (i < Nn)
        d = g_cnt[i * 4] + g_cnt[i * 4 + 1] + g_cnt[i * 4 + 2] + g_cnt[i * 4 + 3];
    int v = d;
    #pragma unroll
    for (int off = 1; off < 32; off <<= 1) {
        int t = __shfl_up_sync(0xFFFFFFFF, v, off);
        if (lane >= off) v += t;
    }
    if (lane == 31) sh_w[warp] = v;
    __syncthreads();
    if (warp == 0) {
        int s = sh_w[lane];
        #pragma unroll
        for (int off = 1; off < 32; off <<= 1) {
            int t = __shfl_up_sync(0xFFFFFFFF, s, off);
            if (lane >= off) s += t;
        }
        sh_w[lane] = s;
    }
    __syncthreads();
    int excl = v - d + (warp > 0 ? sh_w[warp - 1] : 0);
    if (i < Nn) g_rowptr[i] = excl;
    if (tid == 1023) g_bsum[blockIdx.x] = excl + d;
}

__global__ void scanB_k() {
    if (threadIdx.x == 0) {
        int acc = 0;
        for (int b = 0; b < SCAN_NB; b++) {
            g_boff[b] = acc;
            acc += g_bsum[b];
        }
        g_rowptr[Nn] = acc;
    }
}

__global__ __launch_bounds__(1024) void scanC_k() {
    int i = blockIdx.x * 1024 + threadIdx.x;
    if (i < Nn) {
        int r = g_rowptr[i] + g_boff[blockIdx.x];
        g_rowptr[i] = r;
        g_woff[i] = r;
    }
}

__global__ void fill_k(const int* __restrict__ src, const int* __restrict__ dst,
                       const int* __restrict__ et)
{
    int stride = gridDim.x * blockDim.x;
    for (int e = blockIdx.x * blockDim.x + threadIdx.x; e < EE; e += stride) {
        int d = dst[e];
        int pos = atomicAdd(&g_woff[d], 1);
        g_eidx[pos] = (uint32_t)src[e] | ((uint32_t)et[e] << 16);
    }
}

// ---------------- layer-1 aggregation (warp per node) -> g_hacc ----------------
// depends only on g_H1 (relations) + CSR; overlaps with the root gemm pass.
__global__ __launch_bounds__(256) void agg1_k() {
    int lane = threadIdx.x & 31;
    int node = (blockIdx.x * blockDim.x + threadIdx.x) >> 5;
    if (node >= Nn) return;

    int beg = g_rowptr[node], end = g_rowptr[node + 1];
    const float4* __restrict__ H = (const float4*)g_H1;
    const float* __restrict__ nrm = g_norm + node * RR;

    float4 acc = make_float4(0.f, 0.f, 0.f, 0.f);
    int e = beg;
    for (; e + 4 <= end; e += 4) {
        uint32_t u0 = g_eidx[e], u1 = g_eidx[e + 1], u2 = g_eidx[e + 2], u3 = g_eidx[e + 3];
        int s0 = u0 & 0xFFFF, t0 = u0 >> 16;
        int s1 = u1 & 0xFFFF, t1 = u1 >> 16;
        int s2 = u2 & 0xFFFF, t2 = u2 >> 16;
        int s3 = u3 & 0xFFFF, t3 = u3 >> 16;
        float4 v0 = H[((size_t)t0 * Nn + s0) * 32 + lane];
        float4 v1 = H[((size_t)t1 * Nn + s1) * 32 + lane];
        float4 v2 = H[((size_t)t2 * Nn + s2) * 32 + lane];
        float4 v3 = H[((size_t)t3 * Nn + s3) * 32 + lane];
        float w0 = nrm[t0], w1 = nrm[t1], w2 = nrm[t2], w3 = nrm[t3];
        acc.x += w0 * v0.x + w1 * v1.x + w2 * v2.x + w3 * v3.x;
        acc.y += w0 * v0.y + w1 * v1.y + w2 * v2.y + w3 * v3.y;
        acc.z += w0 * v0.z + w1 * v1.z + w2 * v2.z + w3 * v3.z;
        acc.w += w0 * v0.w + w1 * v1.w + w2 * v2.w + w3 * v3.w;
    }
    for (; e < end; e++) {
        uint32_t u = g_eidx[e];
        int s = u & 0xFFFF, t = u >> 16;
        float w = nrm[t];
        float4 v = H[((size_t)t * Nn + s) * 32 + lane];
        acc.x += w * v.x; acc.y += w * v.y; acc.z += w * v.z; acc.w += w * v.w;
    }

    ((float4*)g_hacc)[(size_t)node * 32 + lane] = acc;
}

// ---------------- merge: h = relu(root + agg) ----------------
__global__ void merge_relu_k() {
    size_t total = (size_t)Nn * HID / 4;
    size_t stride = (size_t)gridDim.x * blockDim.x;
    float4* h = (float4*)g_h;
    const float4* a = (const float4*)g_hacc;
    for (size_t i = blockIdx.x * (size_t)blockDim.x + threadIdx.x; i < total; i += stride) {
        float4 r = h[i], v = a[i];
        r.x = fmaxf(r.x + v.x, 0.f);
        r.y = fmaxf(r.y + v.y, 0.f);
        r.z = fmaxf(r.z + v.z, 0.f);
        r.w = fmaxf(r.w + v.w, 0.f);
        h[i] = r;
    }
}

// ---------------- layer-2 GEMM, all 5 z fused ----------------
__global__ __launch_bounds__(256) void gemm2f_k(
    const float* __restrict__ W2,
    const float* __restrict__ root2,
    const float* __restrict__ b2,
    float* __restrict__ out)
{
    extern __shared__ float Bs[];   // [(RR+1)][HID][OUTD]
    for (int i = threadIdx.x; i < (RR + 1) * HID * OUTD; i += blockDim.x) {
        int z = i / (HID * OUTD);
        int rem = i % (HID * OUTD);
        Bs[i] = (z < RR) ? W2[(size_t)z * HID * OUTD + rem] : root2[rem];
    }
    __syncthreads();

    int warp = threadIdx.x >> 5, lane = threadIdx.x & 31;
    int row = blockIdx.x * 8 + warp;
    if (row >= Nn) return;

    const float* a = g_h + (size_t)row * HID;
    #pragma unroll
    for (int z = 0; z <= RR; z++) {
        const float* B = Bs + z * HID * OUTD;
        float acc = (z == RR) ? b2[lane] : 0.f;
        #pragma unroll
        for (int k = 0; k < HID; k += 4) {
            float4 av = *reinterpret_cast<const float4*>(a + k);
            acc += av.x * B[(k + 0) * OUTD + lane];
            acc += av.y * B[(k + 1) * OUTD + lane];
            acc += av.z * B[(k + 2) * OUTD + lane];
            acc += av.w * B[(k + 3) * OUTD + lane];
        }
        if (z < RR) g_H2[((size_t)z * Nn + row) * OUTD + lane] = acc;
        else        out[(size_t)row * OUTD + lane] = acc;
    }
}

// ---------------- layer-2 aggregation (warp per node), MLP-8 gather ----------------
__global__ __launch_bounds__(256) void agg2_k(float* __restrict__ out) {
    int lane = threadIdx.x & 31;
    int node = (blockIdx.x * blockDim.x + threadIdx.x) >> 5;
    if (node >= Nn) return;

    int beg = g_rowptr[node], end = g_rowptr[node + 1];
    const float* __restrict__ H = g_H2;
    const float* __restrict__ nrm = g_norm + node * RR;

    float acc = 0.f;
    int e = beg;
    for (; e + 8 <= end; e += 8) {
        uint32_t u[8];
        #pragma unroll
        for (int j = 0; j < 8; j++) u[j] = g_eidx[e + j];
        float v[8];
        #pragma unroll
        for (int j = 0; j < 8; j++) {
            int s = u[j] & 0xFFFF, t = u[j] >> 16;
            v[j] = H[((size_t)t * Nn + s) * OUTD + lane];
        }
        #pragma unroll
        for (int j = 0; j < 8; j++)
            acc += nrm[u[j] >> 16] * v[j];
    }
    for (; e < end; e++) {
        uint32_t u = g_eidx[e];
        int s = u & 0xFFFF, t = u >> 16;
        acc += nrm[t] * H[((size_t)t * Nn + s) * OUTD + lane];
    }

    float* op = out + (size_t)node * OUTD + lane;
    *op = *op + acc;
}

// ---------------- launch ----------------
extern "C" void kernel_launch(void* const* d_in, const int* in_sizes, int n_in,
                              void* d_out, int out_size)
{
    const float* x     = (const float*)d_in[0];
    const int*   ei    = (const int*)  d_in[1];
    const int*   et    = (const int*)  d_in[2];
    const float* W1    = (const float*)d_in[3];
    const float* root1 = (const float*)d_in[4];
    const float* b1    = (const float*)d_in[5];
    const float* W2    = (const float*)d_in[6];
    const float* root2 = (const float*)d_in[7];
    const float* b2    = (const float*)d_in[8];
    float* out = (float*)d_out;

    const int* src = ei;
    const int* dst = ei + EE;

    static bool init_done = false;
    static cudaStream_t s2, s3, s4;
    static cudaEvent_t evFork, evCSR, evJoin3, evRel, evAgg;
    if (!init_done) {
        cudaFuncSetAttribute(gemm1_mma, cudaFuncAttributeMaxDynamicSharedMemorySize, SMEM_SZ);
        cudaFuncSetAttribute(gemm2f_k, cudaFuncAttributeMaxDynamicSharedMemorySize, GEMM2_SMEM);
        cudaStreamCreateWithFlags(&s2, cudaStreamNonBlocking);
        cudaStreamCreateWithFlags(&s3, cudaStreamNonBlocking);
        cudaStreamCreateWithFlags(&s4, cudaStreamNonBlocking);
        cudaEventCreateWithFlags(&evFork, cudaEventDisableTiming);
        cudaEventCreateWithFlags(&evCSR, cudaEventDisableTiming);
        cudaEventCreateWithFlags(&evJoin3, cudaEventDisableTiming);
        cudaEventCreateWithFlags(&evRel, cudaEventDisableTiming);
        cudaEventCreateWithFlags(&evAgg, cudaEventDisableTiming);
        init_done = true;
    }

    // ---- fork s2: CSR build, concurrent with conv+gemm1 on main ----
    cudaEventRecord(evFork, 0);
    cudaStreamWaitEvent(s2, evFork, 0);
    zero_cnt_k<<<(Nn * RR + 1023) / 1024, 1024, 0, s2>>>();
    count_k   <<<2048, 256, 0, s2>>>(dst, et);
    norm_k    <<<(Nn * RR + 1023) / 1024, 1024, 0, s2>>>();
    scanA_k   <<<SCAN_NB, 1024, 0, s2>>>();
    scanB_k   <<<1, 32, 0, s2>>>();
    scanC_k   <<<SCAN_NB, 1024, 0, s2>>>();
    fill_k    <<<2048, 256, 0, s2>>>(src, dst, et);
    cudaEventRecord(evCSR, s2);

    // ---- fork s3: weight transpose, concurrent with conv_x ----
    cudaStreamWaitEvent(s3, evFork, 0);
    {
        dim3 gw(IND / 32, HID / 32, RR + 1);
        conv_w_t<<<gw, 256, 0, s3>>>(W1, root1);
    }
    cudaEventRecord(evJoin3, s3);

    // ---- main: x convert, then layer-1 GEMM (relations, then root) ----
    conv_x_k<<<2048, 256>>>(x);
    cudaStreamWaitEvent(0, evJoin3, 0);

    {
        dim3 g1(MTILES, 1, RR);
        gemm1_mma<<<g1, 256, SMEM_SZ>>>(b1, 0);      // relations z=0..3
    }
    cudaEventRecord(evRel, 0);
    {
        dim3 g1r(MTILES, 1, 1);
        gemm1_mma<<<g1r, 256, SMEM_SZ>>>(b1, RR);    // root z=4 (overlaps agg1)
    }

    // ---- s4: agg1 (needs relations + CSR only) overlaps the root gemm ----
    cudaStreamWaitEvent(s4, evRel, 0);
    cudaStreamWaitEvent(s4, evCSR, 0);
    agg1_k<<<(Nn * 32 + 255) / 256, 256, 0, s4>>>();
    cudaEventRecord(evAgg, s4);

    // ---- main: merge + layer 2 ----
    cudaStreamWaitEvent(0, evAgg, 0);
    merge_relu_k<<<2048, 256>>>();
    gemm2f_k<<<(Nn + 7) / 8, 256, GEMM2_SMEM>>>(W2, root2, b2, out);
    agg2_k<<<(Nn * 32 + 255) / 256, 256>>>(out);
}

// round 14
// speedup vs baseline: 1.0722x; 1.0722x over previous
#include <cuda_runtime.h>
#include <cuda_fp16.h>
#include <cstdint>

#define Nn   50000
#define IND  1024
#define HID  128
#define OUTD 32
#define RR   4
#define EE   1600000

#define BK     64
#define NCHUNK (IND / BK)             // 16
#define MTILES ((Nn + 127) / 128)     // 391

#define ROW_B   144                   // 64 fp16 = 128B + 16B pad (conflict-free ldmatrix)
#define TILE_B  (128 * ROW_B)         // 18432
#define STAGE_B (2 * TILE_B)          // A, B = 36864
#define SMEM_SZ (2 * STAGE_B)         // 73728, double-buffered; 2 CTAs/SM

#define GEMM2_SMEM ((RR + 1) * HID * OUTD * 4)   // 81920 bytes

#define SCAN_NB ((Nn + 1023) / 1024)  // 49

// ---------------- device scratch ----------------
__device__ float g_H1[(size_t)RR * Nn * HID];
__device__ float g_h [(size_t)Nn * HID];
__device__ float g_H2[(size_t)RR * Nn * OUTD];
__device__ float g_norm[Nn * RR];
__device__ int   g_cnt [Nn * RR];
__device__ int   g_rowptr[Nn + 1];
__device__ int   g_woff  [Nn];
__device__ int   g_bsum  [SCAN_NB];
__device__ int   g_boff  [SCAN_NB];
__device__ uint32_t g_eidx[EE];
__device__ __align__(16) __half g_xh[(size_t)Nn * IND];
__device__ __align__(16) __half g_wt[(size_t)(RR + 1) * HID * IND];  // [z][n][k]

// ---------------- PTX helpers (baseline ISA only — no tcgen05) ----------------
__device__ __forceinline__ uint32_t smem_u32(const void* p) {
    uint32_t a;
    asm("{ .reg .u64 t; cvta.to.shared.u64 t, %1; cvt.u32.u64 %0, t; }" : "=r"(a) : "l"(p));
    return a;
}

__device__ __forceinline__ void cp16(uint32_t dst, const void* src, int ok) {
    asm volatile("cp.async.cg.shared.global [%0], [%1], 16, %2;"
                 :: "r"(dst), "l"(src), "r"(ok ? 16 : 0) : "memory");
}
#define CP_COMMIT() asm volatile("cp.async.commit_group;" ::: "memory")
#define CP_WAIT(n)  asm volatile("cp.async.wait_group %0;" :: "n"(n) : "memory")

__device__ __forceinline__ void ldm_x4(uint32_t* r, uint32_t addr) {
    asm volatile("ldmatrix.sync.aligned.m8n8.x4.shared.b16 {%0,%1,%2,%3}, [%4];"
                 : "=r"(r[0]), "=r"(r[1]), "=r"(r[2]), "=r"(r[3]) : "r"(addr));
}

__device__ __forceinline__ void mma_fp16(float* c, const uint32_t* a, const uint32_t* b) {
    asm volatile("mma.sync.aligned.m16n8k16.row.col.f32.f16.f16.f32 "
                 "{%0,%1,%2,%3}, {%4,%5,%6,%7}, {%8,%9}, {%0,%1,%2,%3};"
                 : "+f"(c[0]), "+f"(c[1]), "+f"(c[2]), "+f"(c[3])
                 : "r"(a[0]), "r"(a[1]), "r"(a[2]), "r"(a[3]), "r"(b[0]), "r"(b[1]));
}

// ---------------- conversion kernels ----------------
__global__ void conv_x_k(const float* __restrict__ x) {
    size_t total = (size_t)Nn * IND / 4;
    size_t stride = (size_t)gridDim.x * blockDim.x;
    const float4* x4 = (const float4*)x;
    uint2* xo = (uint2*)g_xh;
    for (size_t i = blockIdx.x * (size_t)blockDim.x + threadIdx.x; i < total; i += stride) {
        float4 v = x4[i];
        half2 p0 = __floats2half2_rn(v.x, v.y);
        half2 p1 = __floats2half2_rn(v.z, v.w);
        xo[i] = make_uint2(*(uint32_t*)&p0, *(uint32_t*)&p1);
    }
}

// tiled transpose: W [z][k][n] fp32 -> g_wt [z][n][k] fp16, both sides coalesced
__global__ __launch_bounds__(256) void conv_w_t(const float* __restrict__ W1,
                                                const float* __restrict__ root1)
{
    __shared__ float t[32][33];
    const int z = blockIdx.z;
    const int kt = blockIdx.x * 32;
    const int nt = blockIdx.y * 32;
    const int tx = threadIdx.x & 31, ty = threadIdx.x >> 5;   // 32 x 8
    const float* B = (z < RR) ? (W1 + (size_t)z * IND * HID) : root1;

    #pragma unroll
    for (int j = 0; j < 4; j++)
        t[ty + j * 8][tx] = B[(size_t)(kt + ty + j * 8) * HID + nt + tx];
    __syncthreads();

    #pragma unroll
    for (int j = 0; j < 4; j++) {
        float w = t[tx][ty + j * 8];
        size_t o = (size_t)z * HID * IND + (size_t)(nt + ty + j * 8) * IND + kt + tx;
        g_wt[o] = __float2half_rn(w);
    }
}

// ---------------- layer-1 GEMM: single-pass fp16 mma.sync, BK=64, double-buffered ----------------
// grid (MTILES, 1, 5): x fastest -> each wave shares one B weight set (L2).
__global__ __launch_bounds__(256) void gemm1_mma(const float* __restrict__ b1) {
    extern __shared__ __align__(16) char smem[];
    const int tid = threadIdx.x, lane = tid & 31, wid = tid >> 5;
    const int wm = wid & 3, wn = wid >> 2;          // 4 m-warps x 2 n-warps
    const int rowBase = blockIdx.x * 128;
    const int z = blockIdx.z;
    const uint32_t sb = smem_u32(smem);

    const uint4* __restrict__ xh = (const uint4*)g_xh;
    const uint4* __restrict__ wh = (const uint4*)g_wt + (size_t)z * HID * (IND / 8);

    float acc[2][8][4];
    #pragma unroll
    for (int i = 0; i < 2; i++)
        #pragma unroll
        for (int j = 0; j < 8; j++)
            #pragma unroll
            for (int k = 0; k < 4; k++) acc[i][j][k] = 0.f;

    auto issue = [&](int stage, int ch) {
        uint32_t s = sb + stage * STAGE_B;
        // A: 128 rows x 128B = 1024 cp16 (4 per thread)
        #pragma unroll
        for (int i = 0; i < 4; i++) {
            int idx = i * 256 + tid;          // 0..1023
            int r = idx >> 3, c = idx & 7;
            int row = rowBase + r;
            const uint4* src = xh + (size_t)row * (IND / 8) + ch * 8 + c;
            cp16(s + r * ROW_B + c * 16, src, row < Nn);
        }
        // B: 128 rows x 128B = 1024 cp16 (4 per thread)
        #pragma unroll
        for (int i = 0; i < 4; i++) {
            int idx = i * 256 + tid;
            int r = idx >> 3, c = idx & 7;
            const uint4* src = wh + (size_t)r * (IND / 8) + ch * 8 + c;
            cp16(s + TILE_B + r * ROW_B + c * 16, src, 1);
        }
    };

    issue(0, 0);
    CP_COMMIT();

    for (int ch = 0; ch < NCHUNK; ch++) {
        int st = ch & 1;
        if (ch + 1 < NCHUNK) {
            issue(st ^ 1, ch + 1);
            CP_COMMIT();
            CP_WAIT(1);
        } else {
            CP_WAIT(0);
        }
        __syncthreads();

        uint32_t sA = sb + st * STAGE_B;
        uint32_t sB = sA + TILE_B;

        #pragma unroll
        for (int ks = 0; ks < 4; ks++) {
            uint32_t ah[2][4], b[8][2];
            #pragma unroll
            for (int mi = 0; mi < 2; mi++) {
                int arow = wm * 32 + mi * 16 + (lane & 15);
                uint32_t off = arow * ROW_B + ks * 32 + ((lane >> 4) << 4);
                ldm_x4(ah[mi], sA + off);
            }
            #pragma unroll
            for (int j = 0; j < 4; j++) {
                int brow = wn * 64 + j * 16 + ((lane >> 4) << 3) + (lane & 7);
                uint32_t off = brow * ROW_B + ks * 32 + (((lane >> 3) & 1) << 4);
                uint32_t r[4];
                ldm_x4(r, sB + off);
                b[2 * j][0] = r[0]; b[2 * j][1] = r[1];
                b[2 * j + 1][0] = r[2]; b[2 * j + 1][1] = r[3];
            }
            #pragma unroll
            for (int mi = 0; mi < 2; mi++)
                #pragma unroll
                for (int ni = 0; ni < 8; ni++)
                    mma_fp16(acc[mi][ni], ah[mi], b[ni]);
        }
        __syncthreads();
    }

    float* C = (z < RR) ? (g_H1 + (size_t)z * Nn * HID) : g_h;
    #pragma unroll
    for (int mi = 0; mi < 2; mi++) {
        #pragma unroll
        for (int half = 0; half < 2; half++) {
            int row = rowBase + wm * 32 + mi * 16 + (lane >> 2) + half * 8;
            if (row >= Nn) continue;
            #pragma unroll
            for (int ni = 0; ni < 8; ni++) {
                int col = wn * 64 + ni * 8 + (lane & 3) * 2;
                float v0 = acc[mi][ni][half * 2 + 0];
                float v1 = acc[mi][ni][half * 2 + 1];
                if (z == RR) { v0 += __ldg(b1 + col); v1 += __ldg(b1 + col + 1); }
                *(float2*)(C + (size_t)row * HID + col) = make_float2(v0, v1);
            }
        }
    }
}

// ---------------- degree count / norm ----------------
__global__ void zero_cnt_k() {
    int i = blockIdx.x * blockDim.x + threadIdx.x;
    if (i < Nn * RR) g_cnt[i] = 0;
}

__global__ void count_k(const int* __restrict__ dst, const int* __restrict__ et) {
    int stride = gridDim.x * blockDim.x;
    for (int e = blockIdx.x * blockDim.x + threadIdx.x; e < EE; e += stride)
        atomicAdd(&g_cnt[dst[e] * RR + et[e]], 1);
}

__global__ void norm_k() {
    int i = blockIdx.x * blockDim.x + threadIdx.x;
    if (i < Nn * RR) {
        int c = g_cnt[i];
        g_norm[i] = 1.0f / (float)(c > 0 ? c : 1);
    }
}

// ---------------- CSR build: hierarchical scan (3 kernels), then edge fill ----------------
__global__ __launch_bounds__(1024) void scanA_k() {
    __shared__ int sh_w[32];
    const int tid = threadIdx.x, lane = tid & 31, warp = tid >> 5;
    int i = blockIdx.x * 1024 + tid;
    int d = 0;
    if (i < Nn)
        d = g_cnt[i * 4] + g_cnt[i * 4 + 1] + g_cnt[i * 4 + 2] + g_cnt[i * 4 + 3];
    int v = d;
    #pragma unroll
    for (int off = 1; off < 32; off <<= 1) {
        int t = __shfl_up_sync(0xFFFFFFFF, v, off);
        if (lane >= off) v += t;
    }
    if (lane == 31) sh_w[warp] = v;
    __syncthreads();
    if (warp == 0) {
        int s = sh_w[lane];
        #pragma unroll
        for (int off = 1; off < 32; off <<= 1) {
            int t = __shfl_up_sync(0xFFFFFFFF, s, off);
            if (lane >= off) s += t;
        }
        sh_w[lane] = s;
    }
    __syncthreads();
    int excl = v - d + (warp > 0 ? sh_w[warp - 1] : 0);
    if (i < Nn) g_rowptr[i] = excl;
    if (tid == 1023) g_bsum[blockIdx.x] = excl + d;
}

__global__ void scanB_k() {
    if (threadIdx.x == 0) {
        int acc = 0;
        for (int b = 0; b < SCAN_NB; b++) {
            g_boff[b] = acc;
            acc += g_bsum[b];
        }
        g_rowptr[Nn] = acc;
    }
}

__global__ __launch_bounds__(1024) void scanC_k() {
    int i = blockIdx.x * 1024 + threadIdx.x;
    if (i < Nn) {
        int r = g_rowptr[i] + g_boff[blockIdx.x];
        g_rowptr[i] = r;
        g_woff[i] = r;
    }
}

__global__ void fill_k(const int* __restrict__ src, const int* __restrict__ dst,
                       const int* __restrict__ et)
{
    int stride = gridDim.x * blockDim.x;
    for (int e = blockIdx.x * blockDim.x + threadIdx.x; e < EE; e += stride) {
        int d = dst[e];
        int pos = atomicAdd(&g_woff[d], 1);
        g_eidx[pos] = (uint32_t)src[e] | ((uint32_t)et[e] << 16);
    }
}

// ---------------- layer-1 aggregation (warp per node), fused root add + relu ----------------
__global__ __launch_bounds__(256) void agg1_k() {
    int lane = threadIdx.x & 31;
    int node = (blockIdx.x * blockDim.x + threadIdx.x) >> 5;
    if (node >= Nn) return;

    int beg = g_rowptr[node], end = g_rowptr[node + 1];
    const float4* __restrict__ H = (const float4*)g_H1;
    const float* __restrict__ nrm = g_norm + node * RR;

    float4 acc = make_float4(0.f, 0.f, 0.f, 0.f);
    int e = beg;
    for (; e + 4 <= end; e += 4) {
        uint32_t u0 = g_eidx[e], u1 = g_eidx[e + 1], u2 = g_eidx[e + 2], u3 = g_eidx[e + 3];
        int s0 = u0 & 0xFFFF, t0 = u0 >> 16;
        int s1 = u1 & 0xFFFF, t1 = u1 >> 16;
        int s2 = u2 & 0xFFFF, t2 = u2 >> 16;
        int s3 = u3 & 0xFFFF, t3 = u3 >> 16;
        float4 v0 = H[((size_t)t0 * Nn + s0) * 32 + lane];
        float4 v1 = H[((size_t)t1 * Nn + s1) * 32 + lane];
        float4 v2 = H[((size_t)t2 * Nn + s2) * 32 + lane];
        float4 v3 = H[((size_t)t3 * Nn + s3) * 32 + lane];
        float w0 = nrm[t0], w1 = nrm[t1], w2 = nrm[t2], w3 = nrm[t3];
        acc.x += w0 * v0.x + w1 * v1.x + w2 * v2.x + w3 * v3.x;
        acc.y += w0 * v0.y + w1 * v1.y + w2 * v2.y + w3 * v3.y;
        acc.z += w0 * v0.z + w1 * v1.z + w2 * v2.z + w3 * v3.z;
        acc.w += w0 * v0.w + w1 * v1.w + w2 * v2.w + w3 * v3.w;
    }
    for (; e < end; e++) {
        uint32_t u = g_eidx[e];
        int s = u & 0xFFFF, t = u >> 16;
        float w = nrm[t];
        float4 v = H[((size_t)t * Nn + s) * 32 + lane];
        acc.x += w * v.x; acc.y += w * v.y; acc.z += w * v.z; acc.w += w * v.w;
    }

    float4* hrow = (float4*)g_h + (size_t)node * 32 + lane;
    float4 r = *hrow;                       // root + b (from gemm1 z==4)
    r.x = fmaxf(r.x + acc.x, 0.f);
    r.y = fmaxf(r.y + acc.y, 0.f);
    r.z = fmaxf(r.z + acc.z, 0.f);
    r.w = fmaxf(r.w + acc.w, 0.f);
    *hrow = r;
}

// ---------------- layer-2 GEMM, all 5 z fused ----------------
__global__ __launch_bounds__(256) void gemm2f_k(
    const float* __restrict__ W2,
    const float* __restrict__ root2,
    const float* __restrict__ b2,
    float* __restrict__ out)
{
    extern __shared__ float Bs[];   // [(RR+1)][HID][OUTD]
    for (int i = threadIdx.x; i < (RR + 1) * HID * OUTD; i += blockDim.x) {
        int z = i / (HID * OUTD);
        int rem = i % (HID * OUTD);
        Bs[i] = (z < RR) ? W2[(size_t)z * HID * OUTD + rem] : root2[rem];
    }
    __syncthreads();

    int warp = threadIdx.x >> 5, lane = threadIdx.x & 31;
    int row = blockIdx.x * 8 + warp;
    if (row >= Nn) return;

    const float* a = g_h + (size_t)row * HID;
    #pragma unroll
    for (int z = 0; z <= RR; z++) {
        const float* B = Bs + z * HID * OUTD;
        float acc = (z == RR) ? b2[lane] : 0.f;
        #pragma unroll
        for (int k = 0; k < HID; k += 4) {
            float4 av = *reinterpret_cast<const float4*>(a + k);
            acc += av.x * B[(k + 0) * OUTD + lane];
            acc += av.y * B[(k + 1) * OUTD + lane];
            acc += av.z * B[(k + 2) * OUTD + lane];
            acc += av.w * B[(k + 3) * OUTD + lane];
        }
        if (z < RR) g_H2[((size_t)z * Nn + row) * OUTD + lane] = acc;
        else        out[(size_t)row * OUTD + lane] = acc;
    }
}

// ---------------- layer-2 aggregation (warp per node), MLP-8 gather ----------------
__global__ __launch_bounds__(256) void agg2_k(float* __restrict__ out) {
    int lane = threadIdx.x & 31;
    int node = (blockIdx.x * blockDim.x + threadIdx.x) >> 5;
    if (node >= Nn) return;

    int beg = g_rowptr[node], end = g_rowptr[node + 1];
    const float* __restrict__ H = g_H2;
    const float* __restrict__ nrm = g_norm + node * RR;

    float acc = 0.f;
    int e = beg;
    for (; e + 8 <= end; e += 8) {
        uint32_t u[8];
        #pragma unroll
        for (int j = 0; j < 8; j++) u[j] = g_eidx[e + j];
        float v[8];
        #pragma unroll
        for (int j = 0; j < 8; j++) {
            int s = u[j] & 0xFFFF, t = u[j] >> 16;
            v[j] = H[((size_t)t * Nn + s) * OUTD + lane];
        }
        #pragma unroll
        for (int j = 0; j < 8; j++)
            acc += nrm[u[j] >> 16] * v[j];
    }
    for (; e < end; e++) {
        uint32_t u = g_eidx[e];
        int s = u & 0xFFFF, t = u >> 16;
        acc += nrm[t] * H[((size_t)t * Nn + s) * OUTD + lane];
    }

    float* op = out + (size_t)node * OUTD + lane;
    *op = *op + acc;
}

// ---------------- launch ----------------
extern "C" void kernel_launch(void* const* d_in, const int* in_sizes, int n_in,
                              void* d_out, int out_size)
{
    const float* x     = (const float*)d_in[0];
    const int*   ei    = (const int*)  d_in[1];
    const int*   et    = (const int*)  d_in[2];
    const float* W1    = (const float*)d_in[3];
    const float* root1 = (const float*)d_in[4];
    const float* b1    = (const float*)d_in[5];
    const float* W2    = (const float*)d_in[6];
    const float* root2 = (const float*)d_in[7];
    const float* b2    = (const float*)d_in[8];
    float* out = (float*)d_out;

    const int* src = ei;
    const int* dst = ei + EE;

    static bool init_done = false;
    static cudaStream_t s2, s3;
    static cudaEvent_t evFork, evJoin, evJoin3;
    if (!init_done) {
        cudaFuncSetAttribute(gemm1_mma, cudaFuncAttributeMaxDynamicSharedMemorySize, SMEM_SZ);
        cudaFuncSetAttribute(gemm2f_k, cudaFuncAttributeMaxDynamicSharedMemorySize, GEMM2_SMEM);
        cudaStreamCreateWithFlags(&s2, cudaStreamNonBlocking);
        cudaStreamCreateWithFlags(&s3, cudaStreamNonBlocking);
        cudaEventCreateWithFlags(&evFork, cudaEventDisableTiming);
        cudaEventCreateWithFlags(&evJoin, cudaEventDisableTiming);
        cudaEventCreateWithFlags(&evJoin3, cudaEventDisableTiming);
        init_done = true;
    }

    // ---- fork s2: CSR build, concurrent with conv+gemm1 on main ----
    cudaEventRecord(evFork, 0);
    cudaStreamWaitEvent(s2, evFork, 0);
    zero_cnt_k<<<(Nn * RR + 1023) / 1024, 1024, 0, s2>>>();
    count_k   <<<2048, 256, 0, s2>>>(dst, et);
    norm_k    <<<(Nn * RR + 1023) / 1024, 1024, 0, s2>>>();
    scanA_k   <<<SCAN_NB, 1024, 0, s2>>>();
    scanB_k   <<<1, 32, 0, s2>>>();
    scanC_k   <<<SCAN_NB, 1024, 0, s2>>>();
    fill_k    <<<2048, 256, 0, s2>>>(src, dst, et);
    cudaEventRecord(evJoin, s2);

    // ---- fork s3: weight transpose, concurrent with conv_x ----
    cudaStreamWaitEvent(s3, evFork, 0);
    {
        dim3 gw(IND / 32, HID / 32, RR + 1);
        conv_w_t<<<gw, 256, 0, s3>>>(W1, root1);
    }
    cudaEventRecord(evJoin3, s3);

    // ---- main: x convert, then layer-1 GEMM ----
    conv_x_k<<<2048, 256>>>(x);
    cudaStreamWaitEvent(0, evJoin3, 0);

    dim3 g1(MTILES, 1, RR + 1);
    gemm1_mma<<<g1, 256, SMEM_SZ>>>(b1);

    // ---- join: agg1 needs both gemm1 (main) and CSR (s2) ----
    cudaStreamWaitEvent(0, evJoin, 0);
    agg1_k<<<(Nn * 32 + 255) / 256, 256>>>();

    gemm2f_k<<<(Nn + 7) / 8, 256, GEMM2_SMEM>>>(W2, root2, b2, out);
    agg2_k<<<(Nn * 32 + 255) / 256, 256>>>(out);
}

// round 15
// speedup vs baseline: 1.1188x; 1.0435x over previous
#include <cuda_runtime.h>
#include <cuda_fp16.h>
#include <cstdint>

#define Nn   50000
#define IND  1024
#define HID  128
#define OUTD 32
#define RR   4
#define EE   1600000

#define BK     64
#define NCHUNK (IND / BK)             // 16
#define MTILES ((Nn + 127) / 128)     // 391

#define ROW_B   144                   // 64 fp16 = 128B + 16B pad (conflict-free ldmatrix)
#define TILE_B  (128 * ROW_B)         // 18432
#define STAGE_B (2 * TILE_B)          // A, B = 36864
#define SMEM_SZ (2 * STAGE_B)         // 73728, double-buffered; 2 CTAs/SM

#define GEMM2_SMEM ((RR + 1) * HID * OUTD * 4)   // 81920 bytes

#define SCAN_NB ((Nn + 1023) / 1024)  // 49

// ---------------- device scratch ----------------
__device__ __align__(16) __half g_H1h[(size_t)RR * Nn * HID];   // fp16 L1 projections (51.2 MB)
__device__ float g_h [(size_t)Nn * HID];
__device__ float g_H2[(size_t)RR * Nn * OUTD];
__device__ float g_norm[Nn * RR];
__device__ int   g_cnt [Nn * RR];
__device__ int   g_rowptr[Nn + 1];
__device__ int   g_woff  [Nn];
__device__ int   g_bsum  [SCAN_NB];
__device__ int   g_boff  [SCAN_NB];
__device__ uint32_t g_eidx[EE];
__device__ __align__(16) __half g_xh[(size_t)Nn * IND];
__device__ __align__(16) __half g_wt[(size_t)(RR + 1) * HID * IND];  // [z][n][k]

// ---------------- PTX helpers (baseline ISA only — no tcgen05) ----------------
__device__ __forceinline__ uint32_t smem_u32(const void* p) {
    uint32_t a;
    asm("{ .reg .u64 t; cvta.to.shared.u64 t, %1; cvt.u32.u64 %0, t; }" : "=r"(a) : "l"(p));
    return a;
}

__device__ __forceinline__ void cp16(uint32_t dst, const void* src, int ok) {
    asm volatile("cp.async.cg.shared.global [%0], [%1], 16, %2;"
                 :: "r"(dst), "l"(src), "r"(ok ? 16 : 0) : "memory");
}
#define CP_COMMIT() asm volatile("cp.async.commit_group;" ::: "memory")
#define CP_WAIT(n)  asm volatile("cp.async.wait_group %0;" :: "n"(n) : "memory")

__device__ __forceinline__ void ldm_x4(uint32_t* r, uint32_t addr) {
    asm volatile("ldmatrix.sync.aligned.m8n8.x4.shared.b16 {%0,%1,%2,%3}, [%4];"
                 : "=r"(r[0]), "=r"(r[1]), "=r"(r[2]), "=r"(r[3]) : "r"(addr));
}

__device__ __forceinline__ void mma_fp16(float* c, const uint32_t* a, const uint32_t* b) {
    asm volatile("mma.sync.aligned.m16n8k16.row.col.f32.f16.f16.f32 "
                 "{%0,%1,%2,%3}, {%4,%5,%6,%7}, {%8,%9}, {%0,%1,%2,%3};"
                 : "+f"(c[0]), "+f"(c[1]), "+f"(c[2]), "+f"(c[3])
                 : "r"(a[0]), "r"(a[1]), "r"(a[2]), "r"(a[3]), "r"(b[0]), "r"(b[1]));
}

// ---------------- conversion kernels ----------------
__global__ void conv_x_k(const float* __restrict__ x) {
    size_t total = (size_t)Nn * IND / 4;
    size_t stride = (size_t)gridDim.x * blockDim.x;
    const float4* x4 = (const float4*)x;
    uint2* xo = (uint2*)g_xh;
    for (size_t i = blockIdx.x * (size_t)blockDim.x + threadIdx.x; i < total; i += stride) {
        float4 v = x4[i];
        half2 p0 = __floats2half2_rn(v.x, v.y);
        half2 p1 = __floats2half2_rn(v.z, v.w);
        xo[i] = make_uint2(*(uint32_t*)&p0, *(uint32_t*)&p1);
    }
}

// tiled transpose: W [z][k][n] fp32 -> g_wt [z][n][k] fp16, both sides coalesced
__global__ __launch_bounds__(256) void conv_w_t(const float* __restrict__ W1,
                                                const float* __restrict__ root1)
{
    __shared__ float t[32][33];
    const int z = blockIdx.z;
    const int kt = blockIdx.x * 32;
    const int nt = blockIdx.y * 32;
    const int tx = threadIdx.x & 31, ty = threadIdx.x >> 5;   // 32 x 8
    const float* B = (z < RR) ? (W1 + (size_t)z * IND * HID) : root1;

    #pragma unroll
    for (int j = 0; j < 4; j++)
        t[ty + j * 8][tx] = B[(size_t)(kt + ty + j * 8) * HID + nt + tx];
    __syncthreads();

    #pragma unroll
    for (int j = 0; j < 4; j++) {
        float w = t[tx][ty + j * 8];
        size_t o = (size_t)z * HID * IND + (size_t)(nt + ty + j * 8) * IND + kt + tx;
        g_wt[o] = __float2half_rn(w);
    }
}

// ---------------- layer-1 GEMM: single-pass fp16 mma.sync, BK=64, double-buffered ----------------
// grid (MTILES, 1, 5): x fastest -> each wave shares one B weight set (L2).
// z<4 writes fp16 g_H1h; z==4 writes fp32 g_h (+b1).
__global__ __launch_bounds__(256) void gemm1_mma(const float* __restrict__ b1) {
    extern __shared__ __align__(16) char smem[];
    const int tid = threadIdx.x, lane = tid & 31, wid = tid >> 5;
    const int wm = wid & 3, wn = wid >> 2;          // 4 m-warps x 2 n-warps
    const int rowBase = blockIdx.x * 128;
    const int z = blockIdx.z;
    const uint32_t sb = smem_u32(smem);

    const uint4* __restrict__ xh = (const uint4*)g_xh;
    const uint4* __restrict__ wh = (const uint4*)g_wt + (size_t)z * HID * (IND / 8);

    float acc[2][8][4];
    #pragma unroll
    for (int i = 0; i < 2; i++)
        #pragma unroll
        for (int j = 0; j < 8; j++)
            #pragma unroll
            for (int k = 0; k < 4; k++) acc[i][j][k] = 0.f;

    auto issue = [&](int stage, int ch) {
        uint32_t s = sb + stage * STAGE_B;
        #pragma unroll
        for (int i = 0; i < 4; i++) {
            int idx = i * 256 + tid;          // 0..1023
            int r = idx >> 3, c = idx & 7;
            int row = rowBase + r;
            const uint4* src = xh + (size_t)row * (IND / 8) + ch * 8 + c;
            cp16(s + r * ROW_B + c * 16, src, row < Nn);
        }
        #pragma unroll
        for (int i = 0; i < 4; i++) {
            int idx = i * 256 + tid;
            int r = idx >> 3, c = idx & 7;
            const uint4* src = wh + (size_t)r * (IND / 8) + ch * 8 + c;
            cp16(s + TILE_B + r * ROW_B + c * 16, src, 1);
        }
    };

    issue(0, 0);
    CP_COMMIT();

    for (int ch = 0; ch < NCHUNK; ch++) {
        int st = ch & 1;
        if (ch + 1 < NCHUNK) {
            issue(st ^ 1, ch + 1);
            CP_COMMIT();
            CP_WAIT(1);
        } else {
            CP_WAIT(0);
        }
        __syncthreads();

        uint32_t sA = sb + st * STAGE_B;
        uint32_t sB = sA + TILE_B;

        #pragma unroll
        for (int ks = 0; ks < 4; ks++) {
            uint32_t ah[2][4], b[8][2];
            #pragma unroll
            for (int mi = 0; mi < 2; mi++) {
                int arow = wm * 32 + mi * 16 + (lane & 15);
                uint32_t off = arow * ROW_B + ks * 32 + ((lane >> 4) << 4);
                ldm_x4(ah[mi], sA + off);
            }
            #pragma unroll
            for (int j = 0; j < 4; j++) {
                int brow = wn * 64 + j * 16 + ((lane >> 4) << 3) + (lane & 7);
                uint32_t off = brow * ROW_B + ks * 32 + (((lane >> 3) & 1) << 4);
                uint32_t r[4];
                ldm_x4(r, sB + off);
                b[2 * j][0] = r[0]; b[2 * j][1] = r[1];
                b[2 * j + 1][0] = r[2]; b[2 * j + 1][1] = r[3];
            }
            #pragma unroll
            for (int mi = 0; mi < 2; mi++)
                #pragma unroll
                for (int ni = 0; ni < 8; ni++)
                    mma_fp16(acc[mi][ni], ah[mi], b[ni]);
        }
        __syncthreads();
    }

    if (z < RR) {
        __half* C = g_H1h + (size_t)z * Nn * HID;
        #pragma unroll
        for (int mi = 0; mi < 2; mi++) {
            #pragma unroll
            for (int hf = 0; hf < 2; hf++) {
                int row = rowBase + wm * 32 + mi * 16 + (lane >> 2) + hf * 8;
                if (row >= Nn) continue;
                #pragma unroll
                for (int ni = 0; ni < 8; ni++) {
                    int col = wn * 64 + ni * 8 + (lane & 3) * 2;
                    half2 p = __floats2half2_rn(acc[mi][ni][hf * 2 + 0],
                                                acc[mi][ni][hf * 2 + 1]);
                    *(half2*)(C + (size_t)row * HID + col) = p;
                }
            }
        }
    } else {
        float* C = g_h;
        #pragma unroll
        for (int mi = 0; mi < 2; mi++) {
            #pragma unroll
            for (int hf = 0; hf < 2; hf++) {
                int row = rowBase + wm * 32 + mi * 16 + (lane >> 2) + hf * 8;
                if (row >= Nn) continue;
                #pragma unroll
                for (int ni = 0; ni < 8; ni++) {
                    int col = wn * 64 + ni * 8 + (lane & 3) * 2;
                    float v0 = acc[mi][ni][hf * 2 + 0] + __ldg(b1 + col);
                    float v1 = acc[mi][ni][hf * 2 + 1] + __ldg(b1 + col + 1);
                    *(float2*)(C + (size_t)row * HID + col) = make_float2(v0, v1);
                }
            }
        }
    }
}

// ---------------- degree count / norm ----------------
__global__ void zero_cnt_k() {
    int i = blockIdx.x * blockDim.x + threadIdx.x;
    if (i < Nn * RR) g_cnt[i] = 0;
}

__global__ void count_k(const int* __restrict__ dst, const int* __restrict__ et) {
    int stride = gridDim.x * blockDim.x;
    for (int e = blockIdx.x * blockDim.x + threadIdx.x; e < EE; e += stride)
        atomicAdd(&g_cnt[dst[e] * RR + et[e]], 1);
}

__global__ void norm_k() {
    int i = blockIdx.x * blockDim.x + threadIdx.x;
    if (i < Nn * RR) {
        int c = g_cnt[i];
        g_norm[i] = 1.0f / (float)(c > 0 ? c : 1);
    }
}

// ---------------- CSR build: hierarchical scan (3 kernels), then edge fill ----------------
__global__ __launch_bounds__(1024) void scanA_k() {
    __shared__ int sh_w[32];
    const int tid = threadIdx.x, lane = tid & 31, warp = tid >> 5;
    int i = blockIdx.x * 1024 + tid;
    int d = 0;
    if (i < Nn)
        d = g_cnt[i * 4] + g_cnt[i * 4 + 1] + g_cnt[i * 4 + 2] + g_cnt[i * 4 + 3];
    int v = d;
    #pragma unroll
    for (int off = 1; off < 32; off <<= 1) {
        int t = __shfl_up_sync(0xFFFFFFFF, v, off);
        if (lane >= off) v += t;
    }
    if (lane == 31) sh_w[warp] = v;
    __syncthreads();
    if (warp == 0) {
        int s = sh_w[lane];
        #pragma unroll
        for (int off = 1; off < 32; off <<= 1) {
            int t = __shfl_up_sync(0xFFFFFFFF, s, off);
            if (lane >= off) s += t;
        }
        sh_w[lane] = s;
    }
    __syncthreads();
    int excl = v - d + (warp > 0 ? sh_w[warp - 1] : 0);
    if (i < Nn) g_rowptr[i] = excl;
    if (tid == 1023) g_bsum[blockIdx.x] = excl + d;
}

__global__ void scanB_k() {
    if (threadIdx.x == 0) {
        int acc = 0;
        for (int b = 0; b < SCAN_NB; b++) {
            g_boff[b] = acc;
            acc += g_bsum[b];
        }
        g_rowptr[Nn] = acc;
    }
}

__global__ __launch_bounds__(1024) void scanC_k() {
    int i = blockIdx.x * 1024 + threadIdx.x;
    if (i < Nn) {
        int r = g_rowptr[i] + g_boff[blockIdx.x];
        g_rowptr[i] = r;
        g_woff[i] = r;
    }
}

__global__ void fill_k(const int* __restrict__ src, const int* __restrict__ dst,
                       const int* __restrict__ et)
{
    int stride = gridDim.x * blockDim.x;
    for (int e = blockIdx.x * blockDim.x + threadIdx.x; e < EE; e += stride) {
        int d = dst[e];
        int pos = atomicAdd(&g_woff[d], 1);
        g_eidx[pos] = (uint32_t)src[e] | ((uint32_t)et[e] << 16);
    }
}

// ---------------- layer-1 aggregation (warp per node), fp16 gather, fused root+relu ----------------
__global__ __launch_bounds__(256) void agg1_k() {
    int lane = threadIdx.x & 31;
    int node = (blockIdx.x * blockDim.x + threadIdx.x) >> 5;
    if (node >= Nn) return;

    int beg = g_rowptr[node], end = g_rowptr[node + 1];
    const uint2* __restrict__ H = (const uint2*)g_H1h;   // row = 32 x uint2 (4 halves/lane)
    const float* __restrict__ nrm = g_norm + node * RR;

    float4 acc = make_float4(0.f, 0.f, 0.f, 0.f);
    int e = beg;
    for (; e + 4 <= end; e += 4) {
        uint32_t u0 = g_eidx[e], u1 = g_eidx[e + 1], u2 = g_eidx[e + 2], u3 = g_eidx[e + 3];
        int s0 = u0 & 0xFFFF, t0 = u0 >> 16;
        int s1 = u1 & 0xFFFF, t1 = u1 >> 16;
        int s2 = u2 & 0xFFFF, t2 = u2 >> 16;
        int s3 = u3 & 0xFFFF, t3 = u3 >> 16;
        uint2 a0 = H[((size_t)t0 * Nn + s0) * 32 + lane];
        uint2 a1 = H[((size_t)t1 * Nn + s1) * 32 + lane];
        uint2 a2 = H[((size_t)t2 * Nn + s2) * 32 + lane];
        uint2 a3 = H[((size_t)t3 * Nn + s3) * 32 + lane];
        float w0 = nrm[t0], w1 = nrm[t1], w2 = nrm[t2], w3 = nrm[t3];
        float2 p, q;
        p = __half22float2(*(half2*)&a0.x); q = __half22float2(*(half2*)&a0.y);
        acc.x += w0 * p.x; acc.y += w0 * p.y; acc.z += w0 * q.x; acc.w += w0 * q.y;
        p = __half22float2(*(half2*)&a1.x); q = __half22float2(*(half2*)&a1.y);
        acc.x += w1 * p.x; acc.y += w1 * p.y; acc.z += w1 * q.x; acc.w += w1 * q.y;
        p = __half22float2(*(half2*)&a2.x); q = __half22float2(*(half2*)&a2.y);
        acc.x += w2 * p.x; acc.y += w2 * p.y; acc.z += w2 * q.x; acc.w += w2 * q.y;
        p = __half22float2(*(half2*)&a3.x); q = __half22float2(*(half2*)&a3.y);
        acc.x += w3 * p.x; acc.y += w3 * p.y; acc.z += w3 * q.x; acc.w += w3 * q.y;
    }
    for (; e < end; e++) {
        uint32_t u = g_eidx[e];
        int s = u & 0xFFFF, t = u >> 16;
        float w = nrm[t];
        uint2 a = H[((size_t)t * Nn + s) * 32 + lane];
        float2 p = __half22float2(*(half2*)&a.x), q = __half22float2(*(half2*)&a.y);
        acc.x += w * p.x; acc.y += w * p.y; acc.z += w * q.x; acc.w += w * q.y;
    }

    // g_h row layout: 32 float4 per row; lane owns columns [4*lane, 4*lane+4)
    float4* hrow = (float4*)g_h + (size_t)node * 32 + lane;
    float4 r = *hrow;                       // root + b (from gemm1 z==4)
    r.x = fmaxf(r.x + acc.x, 0.f);
    r.y = fmaxf(r.y + acc.y, 0.f);
    r.z = fmaxf(r.z + acc.z, 0.f);
    r.w = fmaxf(r.w + acc.w, 0.f);
    *hrow = r;
}

// ---------------- layer-2 GEMM, all 5 z fused ----------------
__global__ __launch_bounds__(256) void gemm2f_k(
    const float* __restrict__ W2,
    const float* __restrict__ root2,
    const float* __restrict__ b2,
    float* __restrict__ out)
{
    extern __shared__ float Bs[];   // [(RR+1)][HID][OUTD]
    for (int i = threadIdx.x; i < (RR + 1) * HID * OUTD; i += blockDim.x) {
        int z = i / (HID * OUTD);
        int rem = i % (HID * OUTD);
        Bs[i] = (z < RR) ? W2[(size_t)z * HID * OUTD + rem] : root2[rem];
    }
    __syncthreads();

    int warp = threadIdx.x >> 5, lane = threadIdx.x & 31;
    int row = blockIdx.x * 8 + warp;
    if (row >= Nn) return;

    const float* a = g_h + (size_t)row * HID;
    #pragma unroll
    for (int z = 0; z <= RR; z++) {
        const float* B = Bs + z * HID * OUTD;
        float acc = (z == RR) ? b2[lane] : 0.f;
        #pragma unroll
        for (int k = 0; k < HID; k += 4) {
            float4 av = *reinterpret_cast<const float4*>(a + k);
            acc += av.x * B[(k + 0) * OUTD + lane];
            acc += av.y * B[(k + 1) * OUTD + lane];
            acc += av.z * B[(k + 2) * OUTD + lane];
            acc += av.w * B[(k + 3) * OUTD + lane];
        }
        if (z < RR) g_H2[((size_t)z * Nn + row) * OUTD + lane] = acc;
        else        out[(size_t)row * OUTD + lane] = acc;
    }
}

// ---------------- layer-2 aggregation (warp per node), MLP-8 gather ----------------
__global__ __launch_bounds__(256) void agg2_k(float* __restrict__ out) {
    int lane = threadIdx.x & 31;
    int node = (blockIdx.x * blockDim.x + threadIdx.x) >> 5;
    if (node >= Nn) return;

    int beg = g_rowptr[node], end = g_rowptr[node + 1];
    const float* __restrict__ H = g_H2;
    const float* __restrict__ nrm = g_norm + node * RR;

    float acc = 0.f;
    int e = beg;
    for (; e + 8 <= end; e += 8) {
        uint32_t u[8];
        #pragma unroll
        for (int j = 0; j < 8; j++) u[j] = g_eidx[e + j];
        float v[8];
        #pragma unroll
        for (int j = 0; j < 8; j++) {
            int s = u[j] & 0xFFFF, t = u[j] >> 16;
            v[j] = H[((size_t)t * Nn + s) * OUTD + lane];
        }
        #pragma unroll
        for (int j = 0; j < 8; j++)
            acc += nrm[u[j] >> 16] * v[j];
    }
    for (; e < end; e++) {
        uint32_t u = g_eidx[e];
        int s = u & 0xFFFF, t = u >> 16;
        acc += nrm[t] * H[((size_t)t * Nn + s) * OUTD + lane];
    }

    float* op = out + (size_t)node * OUTD + lane;
    *op = *op + acc;
}

// ---------------- launch ----------------
extern "C" void kernel_launch(void* const* d_in, const int* in_sizes, int n_in,
                              void* d_out, int out_size)
{
    const float* x     = (const float*)d_in[0];
    const int*   ei    = (const int*)  d_in[1];
    const int*   et    = (const int*)  d_in[2];
    const float* W1    = (const float*)d_in[3];
    const float* root1 = (const float*)d_in[4];
    const float* b1    = (const float*)d_in[5];
    const float* W2    = (const float*)d_in[6];
    const float* root2 = (const float*)d_in[7];
    const float* b2    = (const float*)d_in[8];
    float* out = (float*)d_out;

    const int* src = ei;
    const int* dst = ei + EE;

    static bool init_done = false;
    static cudaStream_t s2, s3;
    static cudaEvent_t evFork, evJoin, evJoin3;
    if (!init_done) {
        cudaFuncSetAttribute(gemm1_mma, cudaFuncAttributeMaxDynamicSharedMemorySize, SMEM_SZ);
        cudaFuncSetAttribute(gemm2f_k, cudaFuncAttributeMaxDynamicSharedMemorySize, GEMM2_SMEM);
        cudaStreamCreateWithFlags(&s2, cudaStreamNonBlocking);
        cudaStreamCreateWithFlags(&s3, cudaStreamNonBlocking);
        cudaEventCreateWithFlags(&evFork, cudaEventDisableTiming);
        cudaEventCreateWithFlags(&evJoin, cudaEventDisableTiming);
        cudaEventCreateWithFlags(&evJoin3, cudaEventDisableTiming);
        init_done = true;
    }

    // ---- fork s2: CSR build, concurrent with conv+gemm1 on main ----
    cudaEventRecord(evFork, 0);
    cudaStreamWaitEvent(s2, evFork, 0);
    zero_cnt_k<<<(Nn * RR + 1023) / 1024, 1024, 0, s2>>>();
    count_k   <<<2048, 256, 0, s2>>>(dst, et);
    norm_k    <<<(Nn * RR + 1023) / 1024, 1024, 0, s2>>>();
    scanA_k   <<<SCAN_NB, 1024, 0, s2>>>();
    scanB_k   <<<1, 32, 0, s2>>>();
    scanC_k   <<<SCAN_NB, 1024, 0, s2>>>();
    fill_k    <<<2048, 256, 0, s2>>>(src, dst, et);
    cudaEventRecord(evJoin, s2);

    // ---- fork s3: weight transpose, concurrent with conv_x ----
    cudaStreamWaitEvent(s3, evFork, 0);
    {
        dim3 gw(IND / 32, HID / 32, RR + 1);
        conv_w_t<<<gw, 256, 0, s3>>>(W1, root1);
    }
    cudaEventRecord(evJoin3, s3);

    // ---- main: x convert, then layer-1 GEMM ----
    conv_x_k<<<2048, 256>>>(x);
    cudaStreamWaitEvent(0, evJoin3, 0);

    dim3 g1(MTILES, 1, RR + 1);
    gemm1_mma<<<g1, 256, SMEM_SZ>>>(b1);

    // ---- join: agg1 needs both gemm1 (main) and CSR (s2) ----
    cudaStreamWaitEvent(0, evJoin, 0);
    agg1_k<<<(Nn * 32 + 255) / 256, 256>>>();

    gemm2f_k<<<(Nn + 7) / 8, 256, GEMM2_SMEM>>>(W2, root2, b2, out);
    agg2_k<<<(Nn * 32 + 255) / 256, 256>>>(out);
}

// round 16
// speedup vs baseline: 1.1456x; 1.0239x over previous
#include <cuda_runtime.h>
#include <cuda_fp16.h>
#include <cstdint>

#define Nn   50000
#define IND  1024
#define HID  128
#define OUTD 32
#define RR   4
#define EE   1600000

#define BK     64
#define NCHUNK (IND / BK)             // 16
#define MTILES ((Nn + 127) / 128)     // 391

#define ROW_B   144                   // 64 fp16 = 128B + 16B pad (conflict-free ldmatrix)
#define TILE_B  (128 * ROW_B)         // 18432
#define STAGE_B (2 * TILE_B)          // A, B = 36864
#define SMEM_SZ (2 * STAGE_B)         // 73728, double-buffered; 2 CTAs/SM

#define GEMM2_SMEM ((RR + 1) * HID * OUTD * 4)   // 81920 bytes

#define SCAN_NB ((Nn + 1023) / 1024)  // 49

// ---------------- device scratch ----------------
__device__ __align__(16) __half g_H1h[(size_t)RR * Nn * HID];   // fp16 L1 projections (51.2 MB)
__device__ float g_h [(size_t)Nn * HID];
__device__ __align__(16) __half g_H2h[(size_t)RR * Nn * OUTD];  // fp16 L2 projections (12.8 MB)
__device__ float g_norm[Nn * RR];
__device__ int   g_cnt [Nn * RR];
__device__ int   g_rowptr[Nn + 1];
__device__ int   g_woff  [Nn];
__device__ int   g_bsum  [SCAN_NB];
__device__ int   g_boff  [SCAN_NB];
__device__ uint32_t g_eidx[EE];
__device__ __align__(16) __half g_xh[(size_t)Nn * IND];
__device__ __align__(16) __half g_wt[(size_t)(RR + 1) * HID * IND];  // [z][n][k]

// ---------------- PTX helpers (baseline ISA only — no tcgen05) ----------------
__device__ __forceinline__ uint32_t smem_u32(const void* p) {
    uint32_t a;
    asm("{ .reg .u64 t; cvta.to.shared.u64 t, %1; cvt.u32.u64 %0, t; }" : "=r"(a) : "l"(p));
    return a;
}

__device__ __forceinline__ void cp16(uint32_t dst, const void* src, int ok) {
    asm volatile("cp.async.cg.shared.global [%0], [%1], 16, %2;"
                 :: "r"(dst), "l"(src), "r"(ok ? 16 : 0) : "memory");
}
#define CP_COMMIT() asm volatile("cp.async.commit_group;" ::: "memory")
#define CP_WAIT(n)  asm volatile("cp.async.wait_group %0;" :: "n"(n) : "memory")

__device__ __forceinline__ void ldm_x4(uint32_t* r, uint32_t addr) {
    asm volatile("ldmatrix.sync.aligned.m8n8.x4.shared.b16 {%0,%1,%2,%3}, [%4];"
                 : "=r"(r[0]), "=r"(r[1]), "=r"(r[2]), "=r"(r[3]) : "r"(addr));
}

__device__ __forceinline__ void mma_fp16(float* c, const uint32_t* a, const uint32_t* b) {
    asm volatile("mma.sync.aligned.m16n8k16.row.col.f32.f16.f16.f32 "
                 "{%0,%1,%2,%3}, {%4,%5,%6,%7}, {%8,%9}, {%0,%1,%2,%3};"
                 : "+f"(c[0]), "+f"(c[1]), "+f"(c[2]), "+f"(c[3])
                 : "r"(a[0]), "r"(a[1]), "r"(a[2]), "r"(a[3]), "r"(b[0]), "r"(b[1]));
}

// ---------------- conversion kernels ----------------
__global__ void conv_x_k(const float* __restrict__ x) {
    size_t total = (size_t)Nn * IND / 4;
    size_t stride = (size_t)gridDim.x * blockDim.x;
    const float4* x4 = (const float4*)x;
    uint2* xo = (uint2*)g_xh;
    for (size_t i = blockIdx.x * (size_t)blockDim.x + threadIdx.x; i < total; i += stride) {
        float4 v = x4[i];
        half2 p0 = __floats2half2_rn(v.x, v.y);
        half2 p1 = __floats2half2_rn(v.z, v.w);
        xo[i] = make_uint2(*(uint32_t*)&p0, *(uint32_t*)&p1);
    }
}

// tiled transpose: W [z][k][n] fp32 -> g_wt [z][n][k] fp16, both sides coalesced
__global__ __launch_bounds__(256) void conv_w_t(const float* __restrict__ W1,
                                                const float* __restrict__ root1)
{
    __shared__ float t[32][33];
    const int z = blockIdx.z;
    const int kt = blockIdx.x * 32;
    const int nt = blockIdx.y * 32;
    const int tx = threadIdx.x & 31, ty = threadIdx.x >> 5;   // 32 x 8
    const float* B = (z < RR) ? (W1 + (size_t)z * IND * HID) : root1;

    #pragma unroll
    for (int j = 0; j < 4; j++)
        t[ty + j * 8][tx] = B[(size_t)(kt + ty + j * 8) * HID + nt + tx];
    __syncthreads();

    #pragma unroll
    for (int j = 0; j < 4; j++) {
        float w = t[tx][ty + j * 8];
        size_t o = (size_t)z * HID * IND + (size_t)(nt + ty + j * 8) * IND + kt + tx;
        g_wt[o] = __float2half_rn(w);
    }
}

// ---------------- layer-1 GEMM: single-pass fp16 mma.sync, BK=64, double-buffered ----------------
// grid (MTILES, 1, 5): x fastest -> each wave shares one B weight set (L2).
// z<4 writes fp16 g_H1h; z==4 writes fp32 g_h (+b1).
__global__ __launch_bounds__(256) void gemm1_mma(const float* __restrict__ b1) {
    extern __shared__ __align__(16) char smem[];
    const int tid = threadIdx.x, lane = tid & 31, wid = tid >> 5;
    const int wm = wid & 3, wn = wid >> 2;          // 4 m-warps x 2 n-warps
    const int rowBase = blockIdx.x * 128;
    const int z = blockIdx.z;
    const uint32_t sb = smem_u32(smem);

    const uint4* __restrict__ xh = (const uint4*)g_xh;
    const uint4* __restrict__ wh = (const uint4*)g_wt + (size_t)z * HID * (IND / 8);

    float acc[2][8][4];
    #pragma unroll
    for (int i = 0; i < 2; i++)
        #pragma unroll
        for (int j = 0; j < 8; j++)
            #pragma unroll
            for (int k = 0; k < 4; k++) acc[i][j][k] = 0.f;

    auto issue = [&](int stage, int ch) {
        uint32_t s = sb + stage * STAGE_B;
        #pragma unroll
        for (int i = 0; i < 4; i++) {
            int idx = i * 256 + tid;          // 0..1023
            int r = idx >> 3, c = idx & 7;
            int row = rowBase + r;
            const uint4* src = xh + (size_t)row * (IND / 8) + ch * 8 + c;
            cp16(s + r * ROW_B + c * 16, src, row < Nn);
        }
        #pragma unroll
        for (int i = 0; i < 4; i++) {
            int idx = i * 256 + tid;
            int r = idx >> 3, c = idx & 7;
            const uint4* src = wh + (size_t)r * (IND / 8) + ch * 8 + c;
            cp16(s + TILE_B + r * ROW_B + c * 16, src, 1);
        }
    };

    issue(0, 0);
    CP_COMMIT();

    for (int ch = 0; ch < NCHUNK; ch++) {
        int st = ch & 1;
        if (ch + 1 < NCHUNK) {
            issue(st ^ 1, ch + 1);
            CP_COMMIT();
            CP_WAIT(1);
        } else {
            CP_WAIT(0);
        }
        __syncthreads();

        uint32_t sA = sb + st * STAGE_B;
        uint32_t sB = sA + TILE_B;

        #pragma unroll
        for (int ks = 0; ks < 4; ks++) {
            uint32_t ah[2][4], b[8][2];
            #pragma unroll
            for (int mi = 0; mi < 2; mi++) {
                int arow = wm * 32 + mi * 16 + (lane & 15);
                uint32_t off = arow * ROW_B + ks * 32 + ((lane >> 4) << 4);
                ldm_x4(ah[mi], sA + off);
            }
            #pragma unroll
            for (int j = 0; j < 4; j++) {
                int brow = wn * 64 + j * 16 + ((lane >> 4) << 3) + (lane & 7);
                uint32_t off = brow * ROW_B + ks * 32 + (((lane >> 3) & 1) << 4);
                uint32_t r[4];
                ldm_x4(r, sB + off);
                b[2 * j][0] = r[0]; b[2 * j][1] = r[1];
                b[2 * j + 1][0] = r[2]; b[2 * j + 1][1] = r[3];
            }
            #pragma unroll
            for (int mi = 0; mi < 2; mi++)
                #pragma unroll
                for (int ni = 0; ni < 8; ni++)
                    mma_fp16(acc[mi][ni], ah[mi], b[ni]);
        }
        __syncthreads();
    }

    if (z < RR) {
        __half* C = g_H1h + (size_t)z * Nn * HID;
        #pragma unroll
        for (int mi = 0; mi < 2; mi++) {
            #pragma unroll
            for (int hf = 0; hf < 2; hf++) {
                int row = rowBase + wm * 32 + mi * 16 + (lane >> 2) + hf * 8;
                if (row >= Nn) continue;
                #pragma unroll
                for (int ni = 0; ni < 8; ni++) {
                    int col = wn * 64 + ni * 8 + (lane & 3) * 2;
                    half2 p = __floats2half2_rn(acc[mi][ni][hf * 2 + 0],
                                                acc[mi][ni][hf * 2 + 1]);
                    *(half2*)(C + (size_t)row * HID + col) = p;
                }
            }
        }
    } else {
        float* C = g_h;
        #pragma unroll
        for (int mi = 0; mi < 2; mi++) {
            #pragma unroll
            for (int hf = 0; hf < 2; hf++) {
                int row = rowBase + wm * 32 + mi * 16 + (lane >> 2) + hf * 8;
                if (row >= Nn) continue;
                #pragma unroll
                for (int ni = 0; ni < 8; ni++) {
                    int col = wn * 64 + ni * 8 + (lane & 3) * 2;
                    float v0 = acc[mi][ni][hf * 2 + 0] + __ldg(b1 + col);
                    float v1 = acc[mi][ni][hf * 2 + 1] + __ldg(b1 + col + 1);
                    *(float2*)(C + (size_t)row * HID + col) = make_float2(v0, v1);
                }
            }
        }
    }
}

// ---------------- degree count / norm ----------------
__global__ void zero_cnt_k() {
    int i = blockIdx.x * blockDim.x + threadIdx.x;
    if (i < Nn * RR) g_cnt[i] = 0;
}

__global__ void count_k(const int* __restrict__ dst, const int* __restrict__ et) {
    int stride = gridDim.x * blockDim.x;
    for (int e = blockIdx.x * blockDim.x + threadIdx.x; e < EE; e += stride)
        atomicAdd(&g_cnt[dst[e] * RR + et[e]], 1);
}

__global__ void norm_k() {
    int i = blockIdx.x * blockDim.x + threadIdx.x;
    if (i < Nn * RR) {
        int c = g_cnt[i];
        g_norm[i] = 1.0f / (float)(c > 0 ? c : 1);
    }
}

// ---------------- CSR build: hierarchical scan (3 kernels), then edge fill ----------------
__global__ __launch_bounds__(1024) void scanA_k() {
    __shared__ int sh_w[32];
    const int tid = threadIdx.x, lane = tid & 31, warp = tid >> 5;
    int i = blockIdx.x * 1024 + tid;
    int d = 0;
    if (i < Nn)
        d = g_cnt[i * 4] + g_cnt[i * 4 + 1] + g_cnt[i * 4 + 2] + g_cnt[i * 4 + 3];
    int v = d;
    #pragma unroll
    for (int off = 1; off < 32; off <<= 1) {
        int t = __shfl_up_sync(0xFFFFFFFF, v, off);
        if (lane >= off) v += t;
    }
    if (lane == 31) sh_w[warp] = v;
    __syncthreads();
    if (warp == 0) {
        int s = sh_w[lane];
        #pragma unroll
        for (int off = 1; off < 32; off <<= 1) {
            int t = __shfl_up_sync(0xFFFFFFFF, s, off);
            if (lane >= off) s += t;
        }
        sh_w[lane] = s;
    }
    __syncthreads();
    int excl = v - d + (warp > 0 ? sh_w[warp - 1] : 0);
    if (i < Nn) g_rowptr[i] = excl;
    if (tid == 1023) g_bsum[blockIdx.x] = excl + d;
}

__global__ void scanB_k() {
    if (threadIdx.x == 0) {
        int acc = 0;
        for (int b = 0; b < SCAN_NB; b++) {
            g_boff[b] = acc;
            acc += g_bsum[b];
        }
        g_rowptr[Nn] = acc;
    }
}

__global__ __launch_bounds__(1024) void scanC_k() {
    int i = blockIdx.x * 1024 + threadIdx.x;
    if (i < Nn) {
        int r = g_rowptr[i] + g_boff[blockIdx.x];
        g_rowptr[i] = r;
        g_woff[i] = r;
    }
}

__global__ void fill_k(const int* __restrict__ src, const int* __restrict__ dst,
                       const int* __restrict__ et)
{
    int stride = gridDim.x * blockDim.x;
    for (int e = blockIdx.x * blockDim.x + threadIdx.x; e < EE; e += stride) {
        int d = dst[e];
        int pos = atomicAdd(&g_woff[d], 1);
        g_eidx[pos] = (uint32_t)src[e] | ((uint32_t)et[e] << 16);
    }
}

// ---------------- layer-1 aggregation (warp per node), fp16 gather, fused root+relu ----------------
__global__ __launch_bounds__(256) void agg1_k() {
    int lane = threadIdx.x & 31;
    int node = (blockIdx.x * blockDim.x + threadIdx.x) >> 5;
    if (node >= Nn) return;

    int beg = g_rowptr[node], end = g_rowptr[node + 1];
    const uint2* __restrict__ H = (const uint2*)g_H1h;   // row = 32 x uint2 (4 halves/lane)
    const float* __restrict__ nrm = g_norm + node * RR;

    float4 acc = make_float4(0.f, 0.f, 0.f, 0.f);
    int e = beg;
    for (; e + 4 <= end; e += 4) {
        uint32_t u0 = g_eidx[e], u1 = g_eidx[e + 1], u2 = g_eidx[e + 2], u3 = g_eidx[e + 3];
        int s0 = u0 & 0xFFFF, t0 = u0 >> 16;
        int s1 = u1 & 0xFFFF, t1 = u1 >> 16;
        int s2 = u2 & 0xFFFF, t2 = u2 >> 16;
        int s3 = u3 & 0xFFFF, t3 = u3 >> 16;
        uint2 a0 = H[((size_t)t0 * Nn + s0) * 32 + lane];
        uint2 a1 = H[((size_t)t1 * Nn + s1) * 32 + lane];
        uint2 a2 = H[((size_t)t2 * Nn + s2) * 32 + lane];
        uint2 a3 = H[((size_t)t3 * Nn + s3) * 32 + lane];
        float w0 = nrm[t0], w1 = nrm[t1], w2 = nrm[t2], w3 = nrm[t3];
        float2 p, q;
        p = __half22float2(*(half2*)&a0.x); q = __half22float2(*(half2*)&a0.y);
        acc.x += w0 * p.x; acc.y += w0 * p.y; acc.z += w0 * q.x; acc.w += w0 * q.y;
        p = __half22float2(*(half2*)&a1.x); q = __half22float2(*(half2*)&a1.y);
        acc.x += w1 * p.x; acc.y += w1 * p.y; acc.z += w1 * q.x; acc.w += w1 * q.y;
        p = __half22float2(*(half2*)&a2.x); q = __half22float2(*(half2*)&a2.y);
        acc.x += w2 * p.x; acc.y += w2 * p.y; acc.z += w2 * q.x; acc.w += w2 * q.y;
        p = __half22float2(*(half2*)&a3.x); q = __half22float2(*(half2*)&a3.y);
        acc.x += w3 * p.x; acc.y += w3 * p.y; acc.z += w3 * q.x; acc.w += w3 * q.y;
    }
    for (; e < end; e++) {
        uint32_t u = g_eidx[e];
        int s = u & 0xFFFF, t = u >> 16;
        float w = nrm[t];
        uint2 a = H[((size_t)t * Nn + s) * 32 + lane];
        float2 p = __half22float2(*(half2*)&a.x), q = __half22float2(*(half2*)&a.y);
        acc.x += w * p.x; acc.y += w * p.y; acc.z += w * q.x; acc.w += w * q.y;
    }

    float4* hrow = (float4*)g_h + (size_t)node * 32 + lane;
    float4 r = *hrow;                       // root + b (from gemm1 z==4)
    r.x = fmaxf(r.x + acc.x, 0.f);
    r.y = fmaxf(r.y + acc.y, 0.f);
    r.z = fmaxf(r.z + acc.z, 0.f);
    r.w = fmaxf(r.w + acc.w, 0.f);
    *hrow = r;
}

// ---------------- layer-2 GEMM, all 5 z fused; z<4 writes fp16 ----------------
__global__ __launch_bounds__(256) void gemm2f_k(
    const float* __restrict__ W2,
    const float* __restrict__ root2,
    const float* __restrict__ b2,
    float* __restrict__ out)
{
    extern __shared__ float Bs[];   // [(RR+1)][HID][OUTD]
    for (int i = threadIdx.x; i < (RR + 1) * HID * OUTD; i += blockDim.x) {
        int z = i / (HID * OUTD);
        int rem = i % (HID * OUTD);
        Bs[i] = (z < RR) ? W2[(size_t)z * HID * OUTD + rem] : root2[rem];
    }
    __syncthreads();

    int warp = threadIdx.x >> 5, lane = threadIdx.x & 31;
    int row = blockIdx.x * 8 + warp;
    if (row >= Nn) return;

    const float* a = g_h + (size_t)row * HID;
    #pragma unroll
    for (int z = 0; z <= RR; z++) {
        const float* B = Bs + z * HID * OUTD;
        float acc = (z == RR) ? b2[lane] : 0.f;
        #pragma unroll
        for (int k = 0; k < HID; k += 4) {
            float4 av = *reinterpret_cast<const float4*>(a + k);
            acc += av.x * B[(k + 0) * OUTD + lane];
            acc += av.y * B[(k + 1) * OUTD + lane];
            acc += av.z * B[(k + 2) * OUTD + lane];
            acc += av.w * B[(k + 3) * OUTD + lane];
        }
        if (z < RR) g_H2h[((size_t)z * Nn + row) * OUTD + lane] = __float2half_rn(acc);
        else        out[(size_t)row * OUTD + lane] = acc;
    }
}

// ---------------- layer-2 aggregation (warp per node), fp16 MLP-8 gather ----------------
__global__ __launch_bounds__(256) void agg2_k(float* __restrict__ out) {
    int lane = threadIdx.x & 31;
    int node = (blockIdx.x * blockDim.x + threadIdx.x) >> 5;
    if (node >= Nn) return;

    int beg = g_rowptr[node], end = g_rowptr[node + 1];
    const __half* __restrict__ H = g_H2h;
    const float* __restrict__ nrm = g_norm + node * RR;

    float acc = 0.f;
    int e = beg;
    for (; e + 8 <= end; e += 8) {
        uint32_t u[8];
        #pragma unroll
        for (int j = 0; j < 8; j++) u[j] = g_eidx[e + j];
        float v[8];
        #pragma unroll
        for (int j = 0; j < 8; j++) {
            int s = u[j] & 0xFFFF, t = u[j] >> 16;
            v[j] = __half2float(H[((size_t)t * Nn + s) * OUTD + lane]);
        }
        #pragma unroll
        for (int j = 0; j < 8; j++)
            acc += nrm[u[j] >> 16] * v[j];
    }
    for (; e < end; e++) {
        uint32_t u = g_eidx[e];
        int s = u & 0xFFFF, t = u >> 16;
        acc += nrm[t] * __half2float(H[((size_t)t * Nn + s) * OUTD + lane]);
    }

    float* op = out + (size_t)node * OUTD + lane;
    *op = *op + acc;
}

// ---------------- launch ----------------
extern "C" void kernel_launch(void* const* d_in, const int* in_sizes, int n_in,
                              void* d_out, int out_size)
{
    const float* x     = (const float*)d_in[0];
    const int*   ei    = (const int*)  d_in[1];
    const int*   et    = (const int*)  d_in[2];
    const float* W1    = (const float*)d_in[3];
    const float* root1 = (const float*)d_in[4];
    const float* b1    = (const float*)d_in[5];
    const float* W2    = (const float*)d_in[6];
    const float* root2 = (const float*)d_in[7];
    const float* b2    = (const float*)d_in[8];
    float* out = (float*)d_out;

    const int* src = ei;
    const int* dst = ei + EE;

    static bool init_done = false;
    static cudaStream_t s2, s3;
    static cudaEvent_t evFork, evJoin, evJoin3;
    if (!init_done) {
        cudaFuncSetAttribute(gemm1_mma, cudaFuncAttributeMaxDynamicSharedMemorySize, SMEM_SZ);
        cudaFuncSetAttribute(gemm2f_k, cudaFuncAttributeMaxDynamicSharedMemorySize, GEMM2_SMEM);
        cudaStreamCreateWithFlags(&s2, cudaStreamNonBlocking);
        cudaStreamCreateWithFlags(&s3, cudaStreamNonBlocking);
        cudaEventCreateWithFlags(&evFork, cudaEventDisableTiming);
        cudaEventCreateWithFlags(&evJoin, cudaEventDisableTiming);
        cudaEventCreateWithFlags(&evJoin3, cudaEventDisableTiming);
        init_done = true;
    }

    // ---- fork s2: CSR build, concurrent with conv+gemm1 on main ----
    cudaEventRecord(evFork, 0);
    cudaStreamWaitEvent(s2, evFork, 0);
    zero_cnt_k<<<(Nn * RR + 1023) / 1024, 1024, 0, s2>>>();
    count_k   <<<2048, 256, 0, s2>>>(dst, et);
    norm_k    <<<(Nn * RR + 1023) / 1024, 1024, 0, s2>>>();
    scanA_k   <<<SCAN_NB, 1024, 0, s2>>>();
    scanB_k   <<<1, 32, 0, s2>>>();
    scanC_k   <<<SCAN_NB, 1024, 0, s2>>>();
    fill_k    <<<2048, 256, 0, s2>>>(src, dst, et);
    cudaEventRecord(evJoin, s2);

    // ---- fork s3: weight transpose, concurrent with conv_x ----
    cudaStreamWaitEvent(s3, evFork, 0);
    {
        dim3 gw(IND / 32, HID / 32, RR + 1);
        conv_w_t<<<gw, 256, 0, s3>>>(W1, root1);
    }
    cudaEventRecord(evJoin3, s3);

    // ---- main: x convert, then layer-1 GEMM ----
    conv_x_k<<<2048, 256>>>(x);
    cudaStreamWaitEvent(0, evJoin3, 0);

    dim3 g1(MTILES, 1, RR + 1);
    gemm1_mma<<<g1, 256, SMEM_SZ>>>(b1);

    // ---- join: agg1 needs both gemm1 (main) and CSR (s2) ----
    cudaStreamWaitEvent(0, evJoin, 0);
    agg1_k<<<(Nn * 32 + 255) / 256, 256>>>();

    gemm2f_k<<<(Nn + 7) / 8, 256, GEMM2_SMEM>>>(W2, root2, b2, out);
    agg2_k<<<(Nn * 32 + 255) / 256, 256>>>(out);
}